// round 1
// baseline (speedup 1.0000x reference)
#include <cuda_runtime.h>

// Problem constants (fixed by the reference):
//   u, z: (B=4, C=2048, H=64, W=64) fp32, C = N_T(8) * N_CAPS(16) * CAP_DIM(16)
//   weight: (1,1,3,3,1) -> 9 floats, cross-correlation over (n_t, cap_dim) with wrap pad
//   beta: 1 float
//   v[b,t,c,d,hw] = sum_{kt,kd} w[kt][kd] * u^2[b,(t+kt-1)%8, c, (d+kd-1)%16, hw]
//   out = (z + beta) * rsqrt(v + 1e-6)

#define NT   8
#define NC   16
#define CD   16
#define CCH  (NT*NC*CD)   // 2048
#define HWT  32           // hw tile per block
#define NTHREADS 256

__global__ __launch_bounds__(NTHREADS)
void caps_fused_kernel(const float* __restrict__ z,
                       const float* __restrict__ u,
                       const float* __restrict__ wgt,
                       const float* __restrict__ beta_p,
                       float* __restrict__ out,
                       int hw_total)               // 4096
{
    __shared__ float usq[NT * CD * HWT];          // 8*16*32 floats = 16 KB

    const int ntile     = hw_total / HWT;         // 128
    const int tilesPerB = NC * ntile;             // 2048

    const int bid  = blockIdx.x;
    const int b    = bid / tilesPerB;
    const int rem  = bid % tilesPerB;
    const int c    = rem / ntile;
    const int tile = rem % ntile;
    const int hw0  = tile * HWT;

    const int tid  = threadIdx.x;

    const int baseB = b * CCH * hw_total;         // fits in int (< 2^25)
    const int cOff  = c * CD;                     // channel offset of this capsule

    // ---------------- Phase 1: load u tile, square into smem (float4) -------
    // 8*16 channel-rows * 32 hw = 4096 floats = 1024 float4.
    #pragma unroll
    for (int i = 0; i < 4; ++i) {
        int e4  = tid + i * NTHREADS;             // 0..1023
        int chl = e4 >> 3;                        // 8 float4 per 32-float row
        int hw4 = e4 & 7;
        int t   = chl >> 4;
        int d   = chl & 15;
        int gch = t * (NC * CD) + cOff + d;
        const float4 v4 = *reinterpret_cast<const float4*>(
            u + baseB + gch * hw_total + hw0 + hw4 * 4);
        float4 s4;
        s4.x = v4.x * v4.x; s4.y = v4.y * v4.y;
        s4.z = v4.z * v4.z; s4.w = v4.w * v4.w;
        *reinterpret_cast<float4*>(&usq[chl * HWT + hw4 * 4]) = s4;
    }
    __syncthreads();

    // ---------------- Phase 2: stencil + normalize ---------------------------
    const float w00 = wgt[0], w01 = wgt[1], w02 = wgt[2];
    const float w10 = wgt[3], w11 = wgt[4], w12 = wgt[5];
    const float w20 = wgt[6], w21 = wgt[7], w22 = wgt[8];
    const float beta = beta_p[0];

    const int t   = tid >> 5;                     // 0..7  (one n_t row per warp)
    const int hwl = tid & 31;                     // hw within tile
    const int tm  = (t + NT - 1) & (NT - 1);
    const int tp  = (t + 1) & (NT - 1);

    // Per-kd row combinations: g_kd[col] = sum_kt w[kt][kd] * usq[t+kt-1][col]
    float g0[CD], g1[CD], g2[CD];
    #pragma unroll
    for (int d = 0; d < CD; ++d) {
        float a = usq[(tm * CD + d) * HWT + hwl];
        float m = usq[(t  * CD + d) * HWT + hwl];
        float p = usq[(tp * CD + d) * HWT + hwl];
        g0[d] = w00 * a + w10 * m + w20 * p;
        g1[d] = w01 * a + w11 * m + w21 * p;
        g2[d] = w02 * a + w12 * m + w22 * p;
    }

    const float* zb = z   + baseB + (t * (NC * CD) + cOff) * hw_total + hw0 + hwl;
    float*       ob = out + baseB + (t * (NC * CD) + cOff) * hw_total + hw0 + hwl;

    #pragma unroll
    for (int d = 0; d < CD; ++d) {
        float v = g0[(d + CD - 1) & (CD - 1)] + g1[d] + g2[(d + 1) & (CD - 1)];
        float zz = zb[d * hw_total];
        ob[d * hw_total] = (zz + beta) * __frsqrt_rn(v + 1e-6f);
    }
}

extern "C" void kernel_launch(void* const* d_in, const int* in_sizes, int n_in,
                              void* d_out, int out_size)
{
    const float* z    = (const float*)d_in[0];
    const float* u    = (const float*)d_in[1];
    const float* wgt  = (const float*)d_in[2];   // 9 floats
    const float* beta = (const float*)d_in[3];   // 1 float
    float* out        = (float*)d_out;

    const int hw_total = 64 * 64;                          // 4096
    const int B        = in_sizes[0] / (CCH * hw_total);   // 4
    const int grid     = B * NC * (hw_total / HWT);        // 8192 blocks

    caps_fused_kernel<<<grid, NTHREADS>>>(z, u, wgt, beta, out, hw_total);
}